// round 2
// baseline (speedup 1.0000x reference)
#include <cuda_runtime.h>

#define D 128
#define TILE_M 64
#define KB 32
#define MAXN 50176

// ---- device scratch (no allocations allowed) ----
__device__ float g_agg[MAXN * D];
__device__ float g_h[MAXN * D];
__device__ float g_x1[MAXN * D];
__device__ float g_sum[D];
__device__ float g_sq[D];
__device__ float g_scale[D];
__device__ float g_shift[D];

// ---- zero agg + stats ----
__global__ void zero_kernel(float4* __restrict__ agg4, int n4,
                            float* __restrict__ ssum, float* __restrict__ ssq) {
    int i = blockIdx.x * blockDim.x + threadIdx.x;
    int stride = gridDim.x * blockDim.x;
    float4 z = make_float4(0.f, 0.f, 0.f, 0.f);
    for (; i < n4; i += stride) agg4[i] = z;
    if (blockIdx.x == 0 && threadIdx.x < D) {
        ssum[threadIdx.x] = 0.f;
        ssq[threadIdx.x] = 0.f;
    }
}

// ---- edge message + scatter-add: one warp per edge (int32 indices!) ----
__global__ __launch_bounds__(256) void edge_kernel(
    const float* __restrict__ x, const int* __restrict__ ei,
    const float* __restrict__ ea, float* __restrict__ agg, int E)
{
    int gw = (blockIdx.x * blockDim.x + threadIdx.x) >> 5;
    int lane = threadIdx.x & 31;
    if (gw >= E) return;
    int s = __ldg(ei + gw);
    int d = __ldg(ei + E + gw);
    float4 xv = __ldg((const float4*)(x + (size_t)s * D) + lane);
    float4 ev = __ldg((const float4*)(ea + (size_t)gw * D) + lane);
    float4 m;
    m.x = fmaxf(xv.x + ev.x, 0.f);
    m.y = fmaxf(xv.y + ev.y, 0.f);
    m.z = fmaxf(xv.z + ev.z, 0.f);
    m.w = fmaxf(xv.w + ev.w, 0.f);
    float* p = agg + (size_t)d * D + lane * 4;
    asm volatile("red.global.add.v4.f32 [%0], {%1,%2,%3,%4};"
                 :: "l"(p), "f"(m.x), "f"(m.y), "f"(m.z), "f"(m.w) : "memory");
}

// ---- fused GEMM: MODE 0 = (x+agg)@W1+b1, write h, accumulate BN stats
//                  MODE 1 = relu(h*scale+shift)@W2+b2, relu, write out ----
template<int MODE>
__global__ __launch_bounds__(128)
void gemm_kernel(const float* __restrict__ A, const float* __restrict__ A2,
                 const float* __restrict__ W, const float* __restrict__ bias,
                 const float* __restrict__ scale, const float* __restrict__ shift,
                 float* __restrict__ out,
                 float* __restrict__ ssum, float* __restrict__ ssq, int M)
{
    __shared__ float W_s[KB][D];            // 16 KB
    __shared__ float t_s[KB][TILE_M + 4];   // transposed input tile, padded
    __shared__ float bn_s[2][D];
    __shared__ float st_s[2][D];

    int t = threadIdx.x;
    int cg = t >> 3;   // 0..15 -> columns cg*8 .. cg*8+7
    int rg = t & 7;    // 0..7  -> rows    rg*8 .. rg*8+7
    int row_base = blockIdx.x * TILE_M;

    if (MODE == 1) {
        bn_s[0][t] = __ldg(scale + t);
        bn_s[1][t] = __ldg(shift + t);
        __syncthreads();
    }

    float acc[8][8];
#pragma unroll
    for (int r = 0; r < 8; r++)
#pragma unroll
        for (int c = 0; c < 8; c++) acc[r][c] = 0.f;

    for (int kb = 0; kb < D; kb += KB) {
        // stage W chunk [KB][D] (coalesced)
#pragma unroll
        for (int i = 0; i < 8; i++) {
            int f4 = i * 128 + t;
            int k  = f4 >> 5;
            int c4 = f4 & 31;
            float4 w = __ldg((const float4*)(W + (size_t)(kb + k) * D) + c4);
            *((float4*)&W_s[k][c4 * 4]) = w;
        }
        // stage input tile transposed: t_s[k][row]
#pragma unroll
        for (int i = 0; i < 4; i++) {
            int f4 = i * 128 + t;
            int r  = f4 >> 3;   // local row 0..63
            int k4 = f4 & 7;    // float4 index along k
            int grow = row_base + r;
            float4 v = make_float4(0.f, 0.f, 0.f, 0.f);
            if (grow < M) {
                float4 a = __ldg((const float4*)(A + (size_t)grow * D + kb) + k4);
                if (MODE == 0) {
                    float4 b = __ldg((const float4*)(A2 + (size_t)grow * D + kb) + k4);
                    v = make_float4(a.x + b.x, a.y + b.y, a.z + b.z, a.w + b.w);
                } else {
                    int k0 = kb + k4 * 4;
                    v.x = fmaxf(fmaf(a.x, bn_s[0][k0 + 0], bn_s[1][k0 + 0]), 0.f);
                    v.y = fmaxf(fmaf(a.y, bn_s[0][k0 + 1], bn_s[1][k0 + 1]), 0.f);
                    v.z = fmaxf(fmaf(a.z, bn_s[0][k0 + 2], bn_s[1][k0 + 2]), 0.f);
                    v.w = fmaxf(fmaf(a.w, bn_s[0][k0 + 3], bn_s[1][k0 + 3]), 0.f);
                }
            }
            int kk = k4 * 4;
            t_s[kk + 0][r] = v.x;
            t_s[kk + 1][r] = v.y;
            t_s[kk + 2][r] = v.z;
            t_s[kk + 3][r] = v.w;
        }
        __syncthreads();

#pragma unroll 8
        for (int k = 0; k < KB; k++) {
            float a[8], w[8];
            const float4* ap = (const float4*)&t_s[k][rg * 8];
            *(float4*)&a[0] = ap[0];
            *(float4*)&a[4] = ap[1];
            const float4* wp = (const float4*)&W_s[k][cg * 8];
            *(float4*)&w[0] = wp[0];
            *(float4*)&w[4] = wp[1];
#pragma unroll
            for (int r = 0; r < 8; r++)
#pragma unroll
                for (int c = 0; c < 8; c++)
                    acc[r][c] = fmaf(a[r], w[c], acc[r][c]);
        }
        __syncthreads();
    }

    float bv[8];
#pragma unroll
    for (int c = 0; c < 8; c++) bv[c] = __ldg(bias + cg * 8 + c);

    if (MODE == 0) {
        st_s[0][t] = 0.f;
        st_s[1][t] = 0.f;
        __syncthreads();
        float csum[8], csq[8];
#pragma unroll
        for (int c = 0; c < 8; c++) { csum[c] = 0.f; csq[c] = 0.f; }
#pragma unroll
        for (int r = 0; r < 8; r++) {
            int row = row_base + rg * 8 + r;
            if (row < M) {
                float o[8];
#pragma unroll
                for (int c = 0; c < 8; c++) {
                    o[c] = acc[r][c] + bv[c];
                    csum[c] += o[c];
                    csq[c]  += o[c] * o[c];
                }
                float4* op = (float4*)(out + (size_t)row * D + cg * 8);
                op[0] = make_float4(o[0], o[1], o[2], o[3]);
                op[1] = make_float4(o[4], o[5], o[6], o[7]);
            }
        }
#pragma unroll
        for (int c = 0; c < 8; c++) {
            atomicAdd(&st_s[0][cg * 8 + c], csum[c]);
            atomicAdd(&st_s[1][cg * 8 + c], csq[c]);
        }
        __syncthreads();
        atomicAdd(&ssum[t], st_s[0][t]);
        atomicAdd(&ssq[t],  st_s[1][t]);
    } else {
#pragma unroll
        for (int r = 0; r < 8; r++) {
            int row = row_base + rg * 8 + r;
            if (row < M) {
                float o[8];
#pragma unroll
                for (int c = 0; c < 8; c++) o[c] = fmaxf(acc[r][c] + bv[c], 0.f);
                float4* op = (float4*)(out + (size_t)row * D + cg * 8);
                op[0] = make_float4(o[0], o[1], o[2], o[3]);
                op[1] = make_float4(o[4], o[5], o[6], o[7]);
            }
        }
    }
}

// ---- fold BN stats + gamma/beta into per-feature scale/shift ----
__global__ void finalize_kernel(const float* __restrict__ ssum, const float* __restrict__ ssq,
                                const float* __restrict__ gamma, const float* __restrict__ beta,
                                float* __restrict__ scale, float* __restrict__ shift, float invN)
{
    int i = threadIdx.x;
    float m  = ssum[i] * invN;
    float v  = fmaf(ssq[i], invN, -m * m);
    float r  = rsqrtf(v + 1e-5f);
    float sc = r * __ldg(gamma + i);
    scale[i] = sc;
    shift[i] = fmaf(-m, sc, __ldg(beta + i));
}

extern "C" void kernel_launch(void* const* d_in, const int* in_sizes, int n_in,
                              void* d_out, int out_size) {
    const float* x     = (const float*)d_in[0];
    const int*   ei    = (const int*)d_in[1];       // int32! (JAX demotes int64)
    const float* ea    = (const float*)d_in[2];
    const float* W1    = (const float*)d_in[3];
    const float* b1    = (const float*)d_in[4];
    const float* gamma = (const float*)d_in[5];
    const float* beta  = (const float*)d_in[6];
    const float* W2    = (const float*)d_in[7];
    const float* b2    = (const float*)d_in[8];

    int M = in_sizes[0] / D;
    int E = in_sizes[2] / D;
    int L = in_sizes[3] / (D * D);

    float *p_agg, *p_h, *p_x1, *p_sum, *p_sq, *p_scale, *p_shift;
    cudaGetSymbolAddress((void**)&p_agg,   g_agg);
    cudaGetSymbolAddress((void**)&p_h,     g_h);
    cudaGetSymbolAddress((void**)&p_x1,    g_x1);
    cudaGetSymbolAddress((void**)&p_sum,   g_sum);
    cudaGetSymbolAddress((void**)&p_sq,    g_sq);
    cudaGetSymbolAddress((void**)&p_scale, g_scale);
    cudaGetSymbolAddress((void**)&p_shift, g_shift);

    int gemm_blocks = (M + TILE_M - 1) / TILE_M;
    int edge_blocks = (E + 7) / 8;          // 8 warps (edges) per 256-thread block
    int n4 = M * (D / 4);
    int zero_blocks = (n4 + 255) / 256;
    if (zero_blocks > 4096) zero_blocks = 4096;

    for (int l = 0; l < L; l++) {
        const float* xin = (l == 0) ? x : p_x1;
        float* xout = (l == L - 1) ? (float*)d_out : p_x1;

        zero_kernel<<<zero_blocks, 256>>>((float4*)p_agg, n4, p_sum, p_sq);
        edge_kernel<<<edge_blocks, 256>>>(xin, ei, ea, p_agg, E);
        gemm_kernel<0><<<gemm_blocks, 128>>>(xin, p_agg,
                                             W1 + (size_t)l * D * D, b1 + (size_t)l * D,
                                             nullptr, nullptr, p_h, p_sum, p_sq, M);
        finalize_kernel<<<1, D>>>(p_sum, p_sq, gamma + (size_t)l * D, beta + (size_t)l * D,
                                  p_scale, p_shift, 1.0f / (float)M);
        gemm_kernel<1><<<gemm_blocks, 128>>>(p_h, nullptr,
                                             W2 + (size_t)l * D * D, b2 + (size_t)l * D,
                                             p_scale, p_shift, xout, nullptr, nullptr, M);
    }
}

// round 3
// speedup vs baseline: 1.0584x; 1.0584x over previous
#include <cuda_runtime.h>

#define D 128
#define TILE_M 64
#define KB 32
#define MAXN 50176

typedef unsigned long long u64;

// packed 2xfp32 FMA: acc = a*b + acc  (FFMA2, sm_103a)
#define FMA2(acc, a, b) \
    asm("fma.rn.f32x2 %0, %1, %2, %0;" : "+l"(acc) : "l"(a), "l"(b))
#define DUP_F32(d, s) \
    asm("mov.b64 %0, {%1, %1};" : "=l"(d) : "f"(s))
#define UNPACK2(lo, hi, p) \
    asm("mov.b64 {%0, %1}, %2;" : "=f"(lo), "=f"(hi) : "l"(p))

// ---- device scratch (no allocations allowed) ----
__device__ float g_agg[MAXN * D];
__device__ float g_h[MAXN * D];
__device__ float g_x1[MAXN * D];
__device__ float g_sum[D];
__device__ float g_sq[D];
__device__ float g_scale[D];
__device__ float g_shift[D];

// ---- zero agg + stats ----
__global__ void zero_kernel(float4* __restrict__ agg4, int n4,
                            float* __restrict__ ssum, float* __restrict__ ssq) {
    int i = blockIdx.x * blockDim.x + threadIdx.x;
    int stride = gridDim.x * blockDim.x;
    float4 z = make_float4(0.f, 0.f, 0.f, 0.f);
    for (; i < n4; i += stride) agg4[i] = z;
    if (blockIdx.x == 0 && threadIdx.x < D) {
        ssum[threadIdx.x] = 0.f;
        ssq[threadIdx.x] = 0.f;
    }
}

// ---- edge message + scatter-add: one warp per edge (int32 indices) ----
__global__ __launch_bounds__(256) void edge_kernel(
    const float* __restrict__ x, const int* __restrict__ ei,
    const float* __restrict__ ea, float* __restrict__ agg, int E)
{
    int gw = (blockIdx.x * blockDim.x + threadIdx.x) >> 5;
    int lane = threadIdx.x & 31;
    if (gw >= E) return;
    int s = __ldg(ei + gw);
    int d = __ldg(ei + E + gw);
    float4 xv = __ldg((const float4*)(x + (size_t)s * D) + lane);
    float4 ev = __ldg((const float4*)(ea + (size_t)gw * D) + lane);
    float4 m;
    m.x = fmaxf(xv.x + ev.x, 0.f);
    m.y = fmaxf(xv.y + ev.y, 0.f);
    m.z = fmaxf(xv.z + ev.z, 0.f);
    m.w = fmaxf(xv.w + ev.w, 0.f);
    float* p = agg + (size_t)d * D + lane * 4;
    asm volatile("red.global.add.v4.f32 [%0], {%1,%2,%3,%4};"
                 :: "l"(p), "f"(m.x), "f"(m.y), "f"(m.z), "f"(m.w) : "memory");
}

// ---- fused GEMM (FFMA2 inner loop):
//  MODE 0 = (x+agg)@W1+b1, write h, accumulate BN stats
//  MODE 1 = relu(h*scale+shift)@W2+b2, relu, write out ----
template<int MODE>
__global__ __launch_bounds__(128)
void gemm_kernel(const float* __restrict__ A, const float* __restrict__ A2,
                 const float* __restrict__ W, const float* __restrict__ bias,
                 const float* __restrict__ scale, const float* __restrict__ shift,
                 float* __restrict__ out,
                 float* __restrict__ ssum, float* __restrict__ ssq, int M)
{
    __shared__ float W_s[KB][D];            // 16 KB
    __shared__ float t_s[KB][TILE_M + 4];   // transposed input tile, padded
    __shared__ float bn_s[2][D];
    __shared__ float st_s[2][D];

    int t = threadIdx.x;
    int cg = t >> 3;   // 0..15 -> columns cg*8 .. cg*8+7
    int rg = t & 7;    // 0..7  -> rows    rg*8 .. rg*8+7
    int row_base = blockIdx.x * TILE_M;

    if (MODE == 1) {
        bn_s[0][t] = __ldg(scale + t);
        bn_s[1][t] = __ldg(shift + t);
        __syncthreads();
    }

    // acc: 8 rows x 4 column-pairs (each u64 = 2 packed fp32)
    u64 accp[8][4];
#pragma unroll
    for (int r = 0; r < 8; r++)
#pragma unroll
        for (int c = 0; c < 4; c++) accp[r][c] = 0ULL;   // bits 0 == {0.f, 0.f}

    for (int kb = 0; kb < D; kb += KB) {
        // stage W chunk [KB][D] (coalesced)
#pragma unroll
        for (int i = 0; i < 8; i++) {
            int f4 = i * 128 + t;
            int k  = f4 >> 5;
            int c4 = f4 & 31;
            float4 w = __ldg((const float4*)(W + (size_t)(kb + k) * D) + c4);
            *((float4*)&W_s[k][c4 * 4]) = w;
        }
        // stage input tile transposed: t_s[k][row]
#pragma unroll
        for (int i = 0; i < 4; i++) {
            int f4 = i * 128 + t;
            int r  = f4 >> 3;   // local row 0..63
            int k4 = f4 & 7;    // float4 index along k
            int grow = row_base + r;
            float4 v = make_float4(0.f, 0.f, 0.f, 0.f);
            if (grow < M) {
                float4 a = __ldg((const float4*)(A + (size_t)grow * D + kb) + k4);
                if (MODE == 0) {
                    float4 b = __ldg((const float4*)(A2 + (size_t)grow * D + kb) + k4);
                    v = make_float4(a.x + b.x, a.y + b.y, a.z + b.z, a.w + b.w);
                } else {
                    int k0 = kb + k4 * 4;
                    v.x = fmaxf(fmaf(a.x, bn_s[0][k0 + 0], bn_s[1][k0 + 0]), 0.f);
                    v.y = fmaxf(fmaf(a.y, bn_s[0][k0 + 1], bn_s[1][k0 + 1]), 0.f);
                    v.z = fmaxf(fmaf(a.z, bn_s[0][k0 + 2], bn_s[1][k0 + 2]), 0.f);
                    v.w = fmaxf(fmaf(a.w, bn_s[0][k0 + 3], bn_s[1][k0 + 3]), 0.f);
                }
            }
            int kk = k4 * 4;
            t_s[kk + 0][r] = v.x;
            t_s[kk + 1][r] = v.y;
            t_s[kk + 2][r] = v.z;
            t_s[kk + 3][r] = v.w;
        }
        __syncthreads();

#pragma unroll 8
        for (int k = 0; k < KB; k++) {
            float a[8];
            const float4* ap = (const float4*)&t_s[k][rg * 8];
            *(float4*)&a[0] = ap[0];
            *(float4*)&a[4] = ap[1];
            // W pairs loaded directly as packed u64 (2x LDS.128)
            ulonglong2 w01 = *(const ulonglong2*)&W_s[k][cg * 8];
            ulonglong2 w23 = *(const ulonglong2*)&W_s[k][cg * 8 + 4];
            u64 wp0 = w01.x, wp1 = w01.y, wp2 = w23.x, wp3 = w23.y;
#pragma unroll
            for (int r = 0; r < 8; r++) {
                u64 ad;
                DUP_F32(ad, a[r]);
                FMA2(accp[r][0], ad, wp0);
                FMA2(accp[r][1], ad, wp1);
                FMA2(accp[r][2], ad, wp2);
                FMA2(accp[r][3], ad, wp3);
            }
        }
        __syncthreads();
    }

    float bv[8];
#pragma unroll
    for (int c = 0; c < 8; c++) bv[c] = __ldg(bias + cg * 8 + c);

    if (MODE == 0) {
        st_s[0][t] = 0.f;
        st_s[1][t] = 0.f;
        __syncthreads();
        float csum[8], csq[8];
#pragma unroll
        for (int c = 0; c < 8; c++) { csum[c] = 0.f; csq[c] = 0.f; }
#pragma unroll
        for (int r = 0; r < 8; r++) {
            int row = row_base + rg * 8 + r;
            if (row < M) {
                float o[8];
#pragma unroll
                for (int cp = 0; cp < 4; cp++)
                    UNPACK2(o[2 * cp], o[2 * cp + 1], accp[r][cp]);
#pragma unroll
                for (int c = 0; c < 8; c++) {
                    o[c] += bv[c];
                    csum[c] += o[c];
                    csq[c]  += o[c] * o[c];
                }
                float4* op = (float4*)(out + (size_t)row * D + cg * 8);
                op[0] = make_float4(o[0], o[1], o[2], o[3]);
                op[1] = make_float4(o[4], o[5], o[6], o[7]);
            }
        }
#pragma unroll
        for (int c = 0; c < 8; c++) {
            atomicAdd(&st_s[0][cg * 8 + c], csum[c]);
            atomicAdd(&st_s[1][cg * 8 + c], csq[c]);
        }
        __syncthreads();
        atomicAdd(&ssum[t], st_s[0][t]);
        atomicAdd(&ssq[t],  st_s[1][t]);
    } else {
#pragma unroll
        for (int r = 0; r < 8; r++) {
            int row = row_base + rg * 8 + r;
            if (row < M) {
                float o[8];
#pragma unroll
                for (int cp = 0; cp < 4; cp++)
                    UNPACK2(o[2 * cp], o[2 * cp + 1], accp[r][cp]);
#pragma unroll
                for (int c = 0; c < 8; c++) o[c] = fmaxf(o[c] + bv[c], 0.f);
                float4* op = (float4*)(out + (size_t)row * D + cg * 8);
                op[0] = make_float4(o[0], o[1], o[2], o[3]);
                op[1] = make_float4(o[4], o[5], o[6], o[7]);
            }
        }
    }
}

// ---- fold BN stats + gamma/beta into per-feature scale/shift ----
__global__ void finalize_kernel(const float* __restrict__ ssum, const float* __restrict__ ssq,
                                const float* __restrict__ gamma, const float* __restrict__ beta,
                                float* __restrict__ scale, float* __restrict__ shift, float invN)
{
    int i = threadIdx.x;
    float m  = ssum[i] * invN;
    float v  = fmaf(ssq[i], invN, -m * m);
    float r  = rsqrtf(v + 1e-5f);
    float sc = r * __ldg(gamma + i);
    scale[i] = sc;
    shift[i] = fmaf(-m, sc, __ldg(beta + i));
}

extern "C" void kernel_launch(void* const* d_in, const int* in_sizes, int n_in,
                              void* d_out, int out_size) {
    const float* x     = (const float*)d_in[0];
    const int*   ei    = (const int*)d_in[1];       // int32 (JAX demotes int64)
    const float* ea    = (const float*)d_in[2];
    const float* W1    = (const float*)d_in[3];
    const float* b1    = (const float*)d_in[4];
    const float* gamma = (const float*)d_in[5];
    const float* beta  = (const float*)d_in[6];
    const float* W2    = (const float*)d_in[7];
    const float* b2    = (const float*)d_in[8];

    int M = in_sizes[0] / D;
    int E = in_sizes[2] / D;
    int L = in_sizes[3] / (D * D);

    float *p_agg, *p_h, *p_x1, *p_sum, *p_sq, *p_scale, *p_shift;
    cudaGetSymbolAddress((void**)&p_agg,   g_agg);
    cudaGetSymbolAddress((void**)&p_h,     g_h);
    cudaGetSymbolAddress((void**)&p_x1,    g_x1);
    cudaGetSymbolAddress((void**)&p_sum,   g_sum);
    cudaGetSymbolAddress((void**)&p_sq,    g_sq);
    cudaGetSymbolAddress((void**)&p_scale, g_scale);
    cudaGetSymbolAddress((void**)&p_shift, g_shift);

    int gemm_blocks = (M + TILE_M - 1) / TILE_M;
    int edge_blocks = (E + 7) / 8;          // 8 warps (edges) per 256-thread block
    int n4 = M * (D / 4);
    int zero_blocks = (n4 + 255) / 256;
    if (zero_blocks > 4096) zero_blocks = 4096;

    for (int l = 0; l < L; l++) {
        const float* xin = (l == 0) ? x : p_x1;
        float* xout = (l == L - 1) ? (float*)d_out : p_x1;

        zero_kernel<<<zero_blocks, 256>>>((float4*)p_agg, n4, p_sum, p_sq);
        edge_kernel<<<edge_blocks, 256>>>(xin, ei, ea, p_agg, E);
        gemm_kernel<0><<<gemm_blocks, 128>>>(xin, p_agg,
                                             W1 + (size_t)l * D * D, b1 + (size_t)l * D,
                                             nullptr, nullptr, p_h, p_sum, p_sq, M);
        finalize_kernel<<<1, D>>>(p_sum, p_sq, gamma + (size_t)l * D, beta + (size_t)l * D,
                                  p_scale, p_shift, 1.0f / (float)M);
        gemm_kernel<1><<<gemm_blocks, 128>>>(p_h, nullptr,
                                             W2 + (size_t)l * D * D, b2 + (size_t)l * D,
                                             p_scale, p_shift, xout, nullptr, nullptr, M);
    }
}

// round 4
// speedup vs baseline: 1.1322x; 1.0697x over previous
#include <cuda_runtime.h>

#define D 128
#define TILE_M 64
#define KB 32
#define MAXN 50176
#define MAXE 524288
#define SCAN_B 1024

typedef unsigned long long u64;

// packed 2xfp32 FMA: acc = a*b + acc  (FFMA2, sm_103a)
#define FMA2(acc, a, b) \
    asm("fma.rn.f32x2 %0, %1, %2, %0;" : "+l"(acc) : "l"(a), "l"(b))
#define DUP_F32(d, s) \
    asm("mov.b64 %0, {%1, %1};" : "=l"(d) : "f"(s))
#define UNPACK2(lo, hi, p) \
    asm("mov.b64 {%0, %1}, %2;" : "=f"(lo), "=f"(hi) : "l"(p))

// ---- device scratch (no allocations allowed) ----
__device__ float g_agg[MAXN * D];   // holds x + sum(relu(x_src+ea)) per node
__device__ float g_h[MAXN * D];
__device__ float g_x1[MAXN * D];
__device__ float g_sum[D];
__device__ float g_sq[D];
__device__ float g_scale[D];
__device__ float g_shift[D];
// CSR build scratch
__device__ int g_cnt[MAXN];
__device__ int g_rowptr[MAXN];
__device__ int g_fill[MAXN];      // after scatter: row end
__device__ int g_perm[MAXE];
__device__ int g_bsum[64];
__device__ int g_boff[64];

// ================= CSR build (once per launch) =================
__global__ void zero_cnt_kernel(int* __restrict__ cnt, int n) {
    int i = blockIdx.x * blockDim.x + threadIdx.x;
    if (i < n) cnt[i] = 0;
}

__global__ void hist_kernel(const int* __restrict__ ei, int* __restrict__ cnt, int E) {
    int i = blockIdx.x * blockDim.x + threadIdx.x;
    if (i < E) atomicAdd(&cnt[__ldg(ei + E + i)], 1);
}

// per-block exclusive scan of cnt -> rowptr, block totals -> bsum
__global__ __launch_bounds__(SCAN_B) void scan1_kernel(
    const int* __restrict__ cnt, int* __restrict__ rowptr,
    int* __restrict__ bsum, int n)
{
    __shared__ int sh[SCAN_B];
    int t = threadIdx.x;
    int i = blockIdx.x * SCAN_B + t;
    int v = (i < n) ? cnt[i] : 0;
    sh[t] = v;
    __syncthreads();
#pragma unroll
    for (int off = 1; off < SCAN_B; off <<= 1) {
        int add = (t >= off) ? sh[t - off] : 0;
        __syncthreads();
        sh[t] += add;
        __syncthreads();
    }
    if (i < n) rowptr[i] = sh[t] - v;        // exclusive within block
    if (t == SCAN_B - 1) bsum[blockIdx.x] = sh[t];
}

__global__ void scan2_kernel(const int* __restrict__ bsum, int* __restrict__ boff, int nb) {
    if (threadIdx.x == 0) {
        int acc = 0;
        for (int b = 0; b < nb; b++) { boff[b] = acc; acc += bsum[b]; }
    }
}

__global__ __launch_bounds__(SCAN_B) void scan3_kernel(
    int* __restrict__ rowptr, int* __restrict__ fill,
    const int* __restrict__ boff, int n)
{
    int i = blockIdx.x * SCAN_B + threadIdx.x;
    if (i < n) {
        int r = rowptr[i] + boff[blockIdx.x];
        rowptr[i] = r;
        fill[i] = r;
    }
}

__global__ void scatter_kernel(const int* __restrict__ ei, int* __restrict__ fill,
                               int* __restrict__ perm, int E) {
    int e = blockIdx.x * blockDim.x + threadIdx.x;
    if (e < E) {
        int d = __ldg(ei + E + e);
        int idx = atomicAdd(&fill[d], 1);
        perm[idx] = e;
    }
}

// ================= per-layer aggregate: warp per node =================
// agg[v] = x[v] + sum_{e: dst=v} relu(x[src_e] + ea[e]); also zeroes BN stats
__global__ __launch_bounds__(256) void agg_kernel(
    const float* __restrict__ x, const int* __restrict__ ei,
    const float* __restrict__ ea,
    const int* __restrict__ rowptr, const int* __restrict__ rowend,
    const int* __restrict__ perm,
    float* __restrict__ agg, float* __restrict__ ssum, float* __restrict__ ssq, int N)
{
    if (blockIdx.x == 0 && threadIdx.x < D) {
        ssum[threadIdx.x] = 0.f;
        ssq[threadIdx.x] = 0.f;
    }
    int v = blockIdx.x * 8 + (threadIdx.x >> 5);
    if (v >= N) return;
    int lane = threadIdx.x & 31;
    int j   = __ldg(rowptr + v);
    int end = __ldg(rowend + v);
    const float4* x4 = (const float4*)x;
    float4 acc = __ldg(x4 + (size_t)v * 32 + lane);
    for (; j < end; j++) {
        int e = __ldg(perm + j);                 // broadcast
        int s = __ldg(ei + e);                   // broadcast (src row)
        float4 xv = __ldg(x4 + (size_t)s * 32 + lane);
        float4 ev = __ldg((const float4*)ea + (size_t)e * 32 + lane);
        acc.x += fmaxf(xv.x + ev.x, 0.f);
        acc.y += fmaxf(xv.y + ev.y, 0.f);
        acc.z += fmaxf(xv.z + ev.z, 0.f);
        acc.w += fmaxf(xv.w + ev.w, 0.f);
    }
    ((float4*)agg)[(size_t)v * 32 + lane] = acc;
}

// ---- fused GEMM (FFMA2 inner loop):
//  MODE 0 = A@W1+b1, write h, accumulate BN stats   (A = x+agg precombined)
//  MODE 1 = relu(A*scale+shift)@W2+b2, relu, write out ----
template<int MODE>
__global__ __launch_bounds__(128)
void gemm_kernel(const float* __restrict__ A,
                 const float* __restrict__ W, const float* __restrict__ bias,
                 const float* __restrict__ scale, const float* __restrict__ shift,
                 float* __restrict__ out,
                 float* __restrict__ ssum, float* __restrict__ ssq, int M)
{
    __shared__ float W_s[KB][D];            // 16 KB
    __shared__ float t_s[KB][TILE_M + 4];   // transposed input tile, padded
    __shared__ float bn_s[2][D];
    __shared__ float st_s[2][D];

    int t = threadIdx.x;
    int cg = t >> 3;   // 0..15 -> columns cg*8 .. cg*8+7
    int rg = t & 7;    // 0..7  -> rows    rg*8 .. rg*8+7
    int row_base = blockIdx.x * TILE_M;

    if (MODE == 1) {
        bn_s[0][t] = __ldg(scale + t);
        bn_s[1][t] = __ldg(shift + t);
        __syncthreads();
    }

    u64 accp[8][4];
#pragma unroll
    for (int r = 0; r < 8; r++)
#pragma unroll
        for (int c = 0; c < 4; c++) accp[r][c] = 0ULL;

    for (int kb = 0; kb < D; kb += KB) {
#pragma unroll
        for (int i = 0; i < 8; i++) {
            int f4 = i * 128 + t;
            int k  = f4 >> 5;
            int c4 = f4 & 31;
            float4 w = __ldg((const float4*)(W + (size_t)(kb + k) * D) + c4);
            *((float4*)&W_s[k][c4 * 4]) = w;
        }
#pragma unroll
        for (int i = 0; i < 4; i++) {
            int f4 = i * 128 + t;
            int r  = f4 >> 3;
            int k4 = f4 & 7;
            int grow = row_base + r;
            float4 v = make_float4(0.f, 0.f, 0.f, 0.f);
            if (grow < M) {
                float4 a = __ldg((const float4*)(A + (size_t)grow * D + kb) + k4);
                if (MODE == 0) {
                    v = a;
                } else {
                    int k0 = kb + k4 * 4;
                    v.x = fmaxf(fmaf(a.x, bn_s[0][k0 + 0], bn_s[1][k0 + 0]), 0.f);
                    v.y = fmaxf(fmaf(a.y, bn_s[0][k0 + 1], bn_s[1][k0 + 1]), 0.f);
                    v.z = fmaxf(fmaf(a.z, bn_s[0][k0 + 2], bn_s[1][k0 + 2]), 0.f);
                    v.w = fmaxf(fmaf(a.w, bn_s[0][k0 + 3], bn_s[1][k0 + 3]), 0.f);
                }
            }
            int kk = k4 * 4;
            t_s[kk + 0][r] = v.x;
            t_s[kk + 1][r] = v.y;
            t_s[kk + 2][r] = v.z;
            t_s[kk + 3][r] = v.w;
        }
        __syncthreads();

#pragma unroll 8
        for (int k = 0; k < KB; k++) {
            float a[8];
            const float4* ap = (const float4*)&t_s[k][rg * 8];
            *(float4*)&a[0] = ap[0];
            *(float4*)&a[4] = ap[1];
            ulonglong2 w01 = *(const ulonglong2*)&W_s[k][cg * 8];
            ulonglong2 w23 = *(const ulonglong2*)&W_s[k][cg * 8 + 4];
            u64 wp0 = w01.x, wp1 = w01.y, wp2 = w23.x, wp3 = w23.y;
#pragma unroll
            for (int r = 0; r < 8; r++) {
                u64 ad;
                DUP_F32(ad, a[r]);
                FMA2(accp[r][0], ad, wp0);
                FMA2(accp[r][1], ad, wp1);
                FMA2(accp[r][2], ad, wp2);
                FMA2(accp[r][3], ad, wp3);
            }
        }
        __syncthreads();
    }

    float bv[8];
#pragma unroll
    for (int c = 0; c < 8; c++) bv[c] = __ldg(bias + cg * 8 + c);

    if (MODE == 0) {
        st_s[0][t] = 0.f;
        st_s[1][t] = 0.f;
        __syncthreads();
        float csum[8], csq[8];
#pragma unroll
        for (int c = 0; c < 8; c++) { csum[c] = 0.f; csq[c] = 0.f; }
#pragma unroll
        for (int r = 0; r < 8; r++) {
            int row = row_base + rg * 8 + r;
            if (row < M) {
                float o[8];
#pragma unroll
                for (int cp = 0; cp < 4; cp++)
                    UNPACK2(o[2 * cp], o[2 * cp + 1], accp[r][cp]);
#pragma unroll
                for (int c = 0; c < 8; c++) {
                    o[c] += bv[c];
                    csum[c] += o[c];
                    csq[c]  += o[c] * o[c];
                }
                float4* op = (float4*)(out + (size_t)row * D + cg * 8);
                op[0] = make_float4(o[0], o[1], o[2], o[3]);
                op[1] = make_float4(o[4], o[5], o[6], o[7]);
            }
        }
#pragma unroll
        for (int c = 0; c < 8; c++) {
            atomicAdd(&st_s[0][cg * 8 + c], csum[c]);
            atomicAdd(&st_s[1][cg * 8 + c], csq[c]);
        }
        __syncthreads();
        atomicAdd(&ssum[t], st_s[0][t]);
        atomicAdd(&ssq[t],  st_s[1][t]);
    } else {
#pragma unroll
        for (int r = 0; r < 8; r++) {
            int row = row_base + rg * 8 + r;
            if (row < M) {
                float o[8];
#pragma unroll
                for (int cp = 0; cp < 4; cp++)
                    UNPACK2(o[2 * cp], o[2 * cp + 1], accp[r][cp]);
#pragma unroll
                for (int c = 0; c < 8; c++) o[c] = fmaxf(o[c] + bv[c], 0.f);
                float4* op = (float4*)(out + (size_t)row * D + cg * 8);
                op[0] = make_float4(o[0], o[1], o[2], o[3]);
                op[1] = make_float4(o[4], o[5], o[6], o[7]);
            }
        }
    }
}

// ---- fold BN stats + gamma/beta into per-feature scale/shift ----
__global__ void finalize_kernel(const float* __restrict__ ssum, const float* __restrict__ ssq,
                                const float* __restrict__ gamma, const float* __restrict__ beta,
                                float* __restrict__ scale, float* __restrict__ shift, float invN)
{
    int i = threadIdx.x;
    float m  = ssum[i] * invN;
    float v  = fmaf(ssq[i], invN, -m * m);
    float r  = rsqrtf(v + 1e-5f);
    float sc = r * __ldg(gamma + i);
    scale[i] = sc;
    shift[i] = fmaf(-m, sc, __ldg(beta + i));
}

extern "C" void kernel_launch(void* const* d_in, const int* in_sizes, int n_in,
                              void* d_out, int out_size) {
    const float* x     = (const float*)d_in[0];
    const int*   ei    = (const int*)d_in[1];       // int32 (JAX demotes int64)
    const float* ea    = (const float*)d_in[2];
    const float* W1    = (const float*)d_in[3];
    const float* b1    = (const float*)d_in[4];
    const float* gamma = (const float*)d_in[5];
    const float* beta  = (const float*)d_in[6];
    const float* W2    = (const float*)d_in[7];
    const float* b2    = (const float*)d_in[8];

    int M = in_sizes[0] / D;      // nodes
    int E = in_sizes[2] / D;      // edges
    int L = in_sizes[3] / (D * D);

    float *p_agg, *p_h, *p_x1, *p_sum, *p_sq, *p_scale, *p_shift;
    int *p_cnt, *p_rowptr, *p_fill, *p_perm, *p_bsum, *p_boff;
    cudaGetSymbolAddress((void**)&p_agg,   g_agg);
    cudaGetSymbolAddress((void**)&p_h,     g_h);
    cudaGetSymbolAddress((void**)&p_x1,    g_x1);
    cudaGetSymbolAddress((void**)&p_sum,   g_sum);
    cudaGetSymbolAddress((void**)&p_sq,    g_sq);
    cudaGetSymbolAddress((void**)&p_scale, g_scale);
    cudaGetSymbolAddress((void**)&p_shift, g_shift);
    cudaGetSymbolAddress((void**)&p_cnt,    g_cnt);
    cudaGetSymbolAddress((void**)&p_rowptr, g_rowptr);
    cudaGetSymbolAddress((void**)&p_fill,   g_fill);
    cudaGetSymbolAddress((void**)&p_perm,   g_perm);
    cudaGetSymbolAddress((void**)&p_bsum,   g_bsum);
    cudaGetSymbolAddress((void**)&p_boff,   g_boff);

    int gemm_blocks = (M + TILE_M - 1) / TILE_M;
    int eb = (E + 255) / 256;
    int nb256 = (M + 255) / 256;
    int nbscan = (M + SCAN_B - 1) / SCAN_B;
    int agg_blocks = (M + 7) / 8;

    // ---- build CSR once (edge_index constant across layers) ----
    zero_cnt_kernel<<<nb256, 256>>>(p_cnt, M);
    hist_kernel<<<eb, 256>>>(ei, p_cnt, E);
    scan1_kernel<<<nbscan, SCAN_B>>>(p_cnt, p_rowptr, p_bsum, M);
    scan2_kernel<<<1, 32>>>(p_bsum, p_boff, nbscan);
    scan3_kernel<<<nbscan, SCAN_B>>>(p_rowptr, p_fill, p_boff, M);
    scatter_kernel<<<eb, 256>>>(ei, p_fill, p_perm, E);
    // after scatter: p_fill[v] == row end of v

    for (int l = 0; l < L; l++) {
        const float* xin = (l == 0) ? x : p_x1;
        float* xout = (l == L - 1) ? (float*)d_out : p_x1;

        agg_kernel<<<agg_blocks, 256>>>(xin, ei, ea, p_rowptr, p_fill, p_perm,
                                        p_agg, p_sum, p_sq, M);
        gemm_kernel<0><<<gemm_blocks, 128>>>(p_agg,
                                             W1 + (size_t)l * D * D, b1 + (size_t)l * D,
                                             nullptr, nullptr, p_h, p_sum, p_sq, M);
        finalize_kernel<<<1, D>>>(p_sum, p_sq, gamma + (size_t)l * D, beta + (size_t)l * D,
                                  p_scale, p_shift, 1.0f / (float)M);
        gemm_kernel<1><<<gemm_blocks, 128>>>(p_h,
                                             W2 + (size_t)l * D * D, b2 + (size_t)l * D,
                                             p_scale, p_shift, xout, nullptr, nullptr, M);
    }
}